// round 14
// baseline (speedup 1.0000x reference)
#include <cuda_runtime.h>
#include <cstdint>

#define NC         100000
#define FEAT       256
#define BATCH      16384
#define F4         64                          // FEAT / 4
#define ATHREADS   256
#define AWPB       8
#define ACC_BLOCKS (BATCH / AWPB)              // 2048 (one warp per sample)
#define CTHREADS   128
#define CWPB       4
#define CPB        128                         // classes scanned per block
#define CLS_BLOCKS ((NC + CPB - 1) / CPB)      // 782

// sum_i ||x_i - t_c||^2 with t = 0.99c + 0.01 s/n expands to
//   [q_i - 1.9602 (x_i.c) + 0.9801 ||c||^2]  summed per sample   (accum)
//   - 0.0199 ||s_c||^2 / n_c                 summed per class    (classpass)
#define A_D 1.9602f
#define A_E 0.9801f
#define A_S 0.0199f

// Scratch — zero at module load; classpass restores the zero invariant.
// g_next needs no invariant (every slot overwritten each replay).
__device__ int      g_head[NC];      // linked-list head, idx+1 (0 = empty)
__device__ float    g_q[NC];         // per-class sum of ||x_i||^2
__device__ int      g_next[BATCH];
__device__ float    g_loss;
__device__ unsigned g_done;

__device__ __forceinline__ void red_add_f32(float* addr, float v) {
    asm volatile("red.global.add.f32 [%0], %1;" :: "l"(addr), "f"(v) : "memory");
}
__device__ __forceinline__ float dot4(float4 a, float4 b) {
    return a.x*b.x + a.y*b.y + a.z*b.z + a.w*b.w;
}
__device__ __forceinline__ void add4(float4& a, float4 b) {
    a.x += b.x; a.y += b.y; a.z += b.z; a.w += b.w;
}

// ---------------------------------------------------------------------------
// Launch 1: one warp per sample (sequential x + gathered center read).
// Per-sample partial q - A_D (x.c) + A_E ||c||^2 -> block aggregate -> one
// g_loss RED per block. Lane 0: RED q into g_q[c] and push sample onto its
// class list (spread atomics).
// ---------------------------------------------------------------------------
__global__ __launch_bounds__(ATHREADS) void accum(const float* __restrict__ x,
                                                  const float* __restrict__ center,
                                                  const int* __restrict__ label) {
    __shared__ float s_part[AWPB];
    int w    = (blockIdx.x * ATHREADS + threadIdx.x) >> 5;  // sample id
    int lane = threadIdx.x & 31;
    int wid  = threadIdx.x >> 5;
    int c    = label[w];                                    // broadcast load

    const float4* xr = reinterpret_cast<const float4*>(x)      + (size_t)w * F4;
    const float4* cr = reinterpret_cast<const float4*>(center) + (size_t)c * F4;
    float4 v0 = xr[lane], v1 = xr[lane + 32];
    float4 c0 = cr[lane], c1 = cr[lane + 32];

    float q = dot4(v0, v0) + dot4(v1, v1);
    float p = q - A_D * (dot4(v0, c0) + dot4(v1, c1))
                + A_E * (dot4(c0, c0) + dot4(c1, c1));
    #pragma unroll
    for (int o = 16; o > 0; o >>= 1) {
        q += __shfl_down_sync(0xFFFFFFFFu, q, o);
        p += __shfl_down_sync(0xFFFFFFFFu, p, o);
    }
    if (lane == 0) {
        s_part[wid] = p;
        red_add_f32(&g_q[c], q);
        g_next[w] = atomicExch(&g_head[c], w + 1);          // list push
    }
    __syncthreads();
    if (threadIdx.x == 0) {
        float b = 0.f;
        #pragma unroll
        for (int i = 0; i < AWPB; i++) b += s_part[i];
        red_add_f32(&g_loss, b);       // 2048 single-addr REDs ~ 1us total
    }
}

// ---------------------------------------------------------------------------
// Launch 2: scan g_head/g_q (coalesced). Each scan THREAD does the single
// g_next hop itself (latency overlapped chip-wide): n=1 classes close with
// -A_S * q inline; multi chains (~1.2K) go to a per-warp walk that counts n
// and accumulates s from x rows. Invariants restored; last block writes out.
// ---------------------------------------------------------------------------
__global__ __launch_bounds__(CTHREADS) void classpass(const float* __restrict__ x,
                                                      float* __restrict__ out) {
    __shared__ int   s_m;
    __shared__ int   s_head[CPB];
    __shared__ float s_wsum[CWPB];

    int tid  = threadIdx.x;
    int lane = tid & 31;
    int wid  = tid >> 5;

    if (tid == 0) s_m = 0;
    __syncthreads();

    float acc = 0.f;
    int c = blockIdx.x * CPB + tid;
    if (c < NC) {
        int h = g_head[c];                     // coalesced 4B scan
        if (h != 0) {
            int   nx = g_next[h - 1];          // scattered, but thread-parallel
            float q  = g_q[c];
            g_head[c] = 0;                     // restore invariants
            g_q[c]    = 0.f;
            if (nx == 0) {
                acc = -A_S * q;                // n = 1: ||s||^2 == q
            } else {
                int p = atomicAdd(&s_m, 1);    // multi: defer to warp stage
                s_head[p] = h;
            }
        }
    }
    __syncthreads();

    int m = s_m;                               // ~1.5 multi chains per block
    for (int i = wid; i < m; i += CWPB) {
        float4 s0 = make_float4(0.f, 0.f, 0.f, 0.f);
        float4 s1 = make_float4(0.f, 0.f, 0.f, 0.f);
        float  n  = 0.f;
        int a = s_head[i] - 1;
        while (a >= 0) {
            int nx = g_next[a];                // broadcast
            const float4* xr = reinterpret_cast<const float4*>(x) + (size_t)a * F4;
            add4(s0, xr[lane]);
            add4(s1, xr[lane + 32]);
            n += 1.f;
            a  = nx - 1;
        }
        float ss = dot4(s0, s0) + dot4(s1, s1);
        #pragma unroll
        for (int o = 16; o > 0; o >>= 1)
            ss += __shfl_down_sync(0xFFFFFFFFu, ss, o);
        if (lane == 0) acc -= A_S * ss / n;
    }

    #pragma unroll
    for (int o = 16; o > 0; o >>= 1)
        acc += __shfl_down_sync(0xFFFFFFFFu, acc, o);
    if (lane == 0) s_wsum[wid] = acc;
    __syncthreads();

    if (tid == 0) {
        float b = 0.f;
        #pragma unroll
        for (int i = 0; i < CWPB; i++) b += s_wsum[i];
        atomicAdd(&g_loss, b);
        __threadfence();
        if (atomicAdd(&g_done, 1u) == (unsigned)(gridDim.x - 1)) {
            out[0] = __ldcg(&g_loss) * (1.f / ((float)BATCH * (float)FEAT));
            g_loss = 0.f;                      // restore invariants
            g_done = 0u;
        }
    }
}

extern "C" void kernel_launch(void* const* d_in, const int* in_sizes, int n_in,
                              void* d_out, int out_size) {
    const float* x      = (const float*)d_in[0];   // batch_feature [16384, 256] f32
    const int*   label  = (const int*)d_in[1];     // batch_label   [16384] int32
    const float* center = (const float*)d_in[2];   // center_feature[100000, 256] f32
    float* out = (float*)d_out;

    accum    <<<ACC_BLOCKS, ATHREADS>>>(x, center, label);
    classpass<<<CLS_BLOCKS, CTHREADS>>>(x, out);
}

// round 15
// speedup vs baseline: 1.2786x; 1.2786x over previous
#include <cuda_runtime.h>
#include <cstdint>

#define NC         100000
#define FEAT       256
#define BATCH      16384
#define F4         64                          // FEAT / 4
#define THREADS    256
#define WPB        8
#define ACC_BLOCKS (BATCH / WPB)               // 2048 (one warp per sample)
#define CPB        256                         // classes scanned per block
#define CLS_BLOCKS ((NC + CPB - 1) / CPB)      // 391

// sum_i ||x_i - t_c||^2 with t = 0.99c + 0.01 s/n expands to
//   [q_i - 1.9602 (x_i.c) + 0.9801 ||c||^2]  summed per sample   (accum)
//   - 0.0199 ||s_c||^2 / n_c                 summed per class    (classpass)
#define A_D 1.9602f
#define A_E 0.9801f
#define A_S 0.0199f

// Scratch — zero at module load; classpass restores the zero invariant.
// g_next needs no invariant (every slot overwritten each replay).
__device__ float2   g_qn[NC];        // {sum ||x_i||^2, count}  (800 KB)
__device__ int      g_head[NC];      // linked-list head, idx+1 (0 = empty)
__device__ int      g_next[BATCH];
__device__ float    g_loss;
__device__ unsigned g_done;

__device__ __forceinline__ void red_add_f32(float* addr, float v) {
    asm volatile("red.global.add.f32 [%0], %1;" :: "l"(addr), "f"(v) : "memory");
}
__device__ __forceinline__ float dot4(float4 a, float4 b) {
    return a.x*b.x + a.y*b.y + a.z*b.z + a.w*b.w;
}
__device__ __forceinline__ void add4(float4& a, float4 b) {
    a.x += b.x; a.y += b.y; a.z += b.z; a.w += b.w;
}

// ---------------------------------------------------------------------------
// Launch 1: one warp per sample (streamed x + gathered center row).
// Per-sample separable loss terms -> block aggregate -> one g_loss RED per
// block. Lane 0: RED {q, 1} into g_qn[c], push sample onto its class list.
// ---------------------------------------------------------------------------
__global__ __launch_bounds__(THREADS) void accum(const float* __restrict__ x,
                                                 const float* __restrict__ center,
                                                 const int* __restrict__ label) {
    __shared__ float s_part[WPB];
    int w    = (blockIdx.x * THREADS + threadIdx.x) >> 5;   // sample id
    int lane = threadIdx.x & 31;
    int wid  = threadIdx.x >> 5;
    int c    = label[w];                                    // broadcast load

    const float4* xr = reinterpret_cast<const float4*>(x)      + (size_t)w * F4;
    const float4* cr = reinterpret_cast<const float4*>(center) + (size_t)c * F4;
    float4 v0 = xr[lane], v1 = xr[lane + 32];
    float4 c0 = cr[lane], c1 = cr[lane + 32];

    float q = dot4(v0, v0) + dot4(v1, v1);
    float p = q - A_D * (dot4(v0, c0) + dot4(v1, c1))
                + A_E * (dot4(c0, c0) + dot4(c1, c1));
    #pragma unroll
    for (int o = 16; o > 0; o >>= 1) {
        q += __shfl_down_sync(0xFFFFFFFFu, q, o);
        p += __shfl_down_sync(0xFFFFFFFFu, p, o);
    }
    if (lane == 0) {
        s_part[wid] = p;
        float* base = reinterpret_cast<float*>(&g_qn[c]);
        red_add_f32(base + 0, q);
        red_add_f32(base + 1, 1.0f);
        g_next[w] = atomicExch(&g_head[c], w + 1);          // list push
    }
    __syncthreads();
    if (threadIdx.x == 0) {
        float b = 0.f;
        #pragma unroll
        for (int i = 0; i < WPB; i++) b += s_part[i];
        red_add_f32(&g_loss, b);       // 2048 no-return REDs on one addr: ~2K cyc
    }
}

// ---------------------------------------------------------------------------
// Launch 2: coalesced float2 scan of g_qn. n известно from the scan — no
// pointer chase. n=1 -> -A_S*q inline; multi (~1.2K classes) -> warp walks
// the chain accumulating s in registers. Invariants restored; last block
// writes d_out.
// ---------------------------------------------------------------------------
__global__ __launch_bounds__(THREADS) void classpass(const float* __restrict__ x,
                                                     float* __restrict__ out) {
    __shared__ int   s_m;
    __shared__ int   s_head[CPB];
    __shared__ float s_n[CPB];
    __shared__ float s_wsum[WPB];

    int tid  = threadIdx.x;
    int lane = tid & 31;
    int wid  = tid >> 5;

    if (tid == 0) s_m = 0;
    __syncthreads();

    float acc = 0.f;
    int c = blockIdx.x * CPB + tid;
    if (c < NC) {
        float2 qn = g_qn[c];                   // coalesced 8B scan
        if (qn.y > 0.f) {
            g_qn[c] = make_float2(0.f, 0.f);   // restore invariants
            if (qn.y == 1.f) {
                acc = -A_S * qn.x;             // n = 1: ||s||^2 == q
                g_head[c] = 0;
            } else {
                int p = atomicAdd(&s_m, 1);    // multi: defer to warp stage
                s_head[p] = g_head[c];
                s_n[p]    = qn.y;
                g_head[c] = 0;
            }
        }
    }
    __syncthreads();

    int m = s_m;                               // ~3 multi chains per block
    for (int i = wid; i < m; i += WPB) {
        float4 s0 = make_float4(0.f, 0.f, 0.f, 0.f);
        float4 s1 = make_float4(0.f, 0.f, 0.f, 0.f);
        int a = s_head[i] - 1;
        while (a >= 0) {                       // avg ~2.2 hops
            int nx = g_next[a];                // broadcast
            const float4* xr = reinterpret_cast<const float4*>(x) + (size_t)a * F4;
            add4(s0, xr[lane]);
            add4(s1, xr[lane + 32]);
            a = nx - 1;
        }
        float ss = dot4(s0, s0) + dot4(s1, s1);
        #pragma unroll
        for (int o = 16; o > 0; o >>= 1)
            ss += __shfl_down_sync(0xFFFFFFFFu, ss, o);
        if (lane == 0) acc -= A_S * ss / s_n[i];
    }

    #pragma unroll
    for (int o = 16; o > 0; o >>= 1)
        acc += __shfl_down_sync(0xFFFFFFFFu, acc, o);
    if (lane == 0) s_wsum[wid] = acc;
    __syncthreads();

    if (tid == 0) {
        float b = 0.f;
        #pragma unroll
        for (int i = 0; i < WPB; i++) b += s_wsum[i];
        atomicAdd(&g_loss, b);
        __threadfence();
        if (atomicAdd(&g_done, 1u) == (unsigned)(gridDim.x - 1)) {
            out[0] = __ldcg(&g_loss) * (1.f / ((float)BATCH * (float)FEAT));
            g_loss = 0.f;                      // restore invariants
            g_done = 0u;
        }
    }
}

extern "C" void kernel_launch(void* const* d_in, const int* in_sizes, int n_in,
                              void* d_out, int out_size) {
    const float* x      = (const float*)d_in[0];   // batch_feature [16384, 256] f32
    const int*   label  = (const int*)d_in[1];     // batch_label   [16384] int32
    const float* center = (const float*)d_in[2];   // center_feature[100000, 256] f32
    float* out = (float*)d_out;

    accum    <<<ACC_BLOCKS, THREADS>>>(x, center, label);
    classpass<<<CLS_BLOCKS, THREADS>>>(x, out);
}

// round 16
// speedup vs baseline: 1.4510x; 1.1348x over previous
#include <cuda_runtime.h>
#include <cstdint>

#define NC         100000
#define FEAT       256
#define BATCH      16384
#define F4         64                          // FEAT / 4
#define THREADS    256
#define WPB        8
#define ACC_BLOCKS (BATCH / WPB)               // 2048 (one warp per sample)
#define CPB        256                         // classes scanned per block
#define CLS_BLOCKS ((NC + CPB - 1) / CPB)      // 391

// contrib_c = Q - 1.9602 D + 0.9801 E - (0.0199/n) ||s||^2
//   Q = sum ||x_i||^2, D = c.s, E = n ||c||^2   (t = 0.99c + 0.01 s/n)
#define A_D 1.9602f
#define A_E 0.9801f
#define A_S 0.0199f

// Scratch — zero at module load; every replay restores the all-zero invariant.
// (g_next needs no invariant: every slot is unconditionally overwritten.)
__device__ float4   g_scal[NC];      // {Q, D, E, n}  (1.6 MB)
__device__ int      g_head[NC];      // linked-list head, idx+1 encoded (0 = empty)
__device__ int      g_next[BATCH];
__device__ float    g_loss;
__device__ unsigned g_done;

__device__ __forceinline__ void red_add_f32(float* addr, float v) {
    asm volatile("red.global.add.f32 [%0], %1;" :: "l"(addr), "f"(v) : "memory");
}
__device__ __forceinline__ float dot4(float4 a, float4 b) {
    return a.x*b.x + a.y*b.y + a.z*b.z + a.w*b.w;
}
__device__ __forceinline__ void add4(float4& a, float4 b) {
    a.x += b.x; a.y += b.y; a.z += b.z; a.w += b.w;
}

// ---------------------------------------------------------------------------
// Launch 1: one warp per sample. Read x row + gathered center row; warp-
// reduce Q, D, E; lane 0 REDs {Q,D,E,1} into g_scal and pushes the sample
// onto its class's linked list (spread atomics).
// ---------------------------------------------------------------------------
__global__ __launch_bounds__(THREADS) void accum(const float* __restrict__ x,
                                                 const float* __restrict__ center,
                                                 const int* __restrict__ label) {
    int w    = (blockIdx.x * THREADS + threadIdx.x) >> 5;   // sample id
    int lane = threadIdx.x & 31;
    int c    = label[w];                                    // broadcast load

    const float4* xr = reinterpret_cast<const float4*>(x)      + (size_t)w * F4;
    const float4* cr = reinterpret_cast<const float4*>(center) + (size_t)c * F4;
    float4 v0 = xr[lane], v1 = xr[lane + 32];
    float4 c0 = cr[lane], c1 = cr[lane + 32];

    float q = dot4(v0, v0) + dot4(v1, v1);
    float d = dot4(v0, c0) + dot4(v1, c1);
    float e = dot4(c0, c0) + dot4(c1, c1);
    #pragma unroll
    for (int o = 16; o > 0; o >>= 1) {
        q += __shfl_down_sync(0xFFFFFFFFu, q, o);
        d += __shfl_down_sync(0xFFFFFFFFu, d, o);
        e += __shfl_down_sync(0xFFFFFFFFu, e, o);
    }
    if (lane == 0) {
        g_next[w] = atomicExch(&g_head[c], w + 1);          // list push
        float* base = reinterpret_cast<float*>(&g_scal[c]);
        red_add_f32(base + 0, q);
        red_add_f32(base + 1, d);
        red_add_f32(base + 2, e);
        red_add_f32(base + 3, 1.0f);
    }
}

// ---------------------------------------------------------------------------
// Launch 2 (PDL): CTAs launch while accum drains; prologue (smem init, index
// math) runs early, cudaGridDependencySynchronize() gates the first read of
// accum-produced data. Then: coalesced scan of g_scal; n=1 closes inline
// (||s||^2 == Q); multi classes get a warp chain-walk over x rows. g_loss
// atomic + last-block writes d_out. All invariants restored.
// ---------------------------------------------------------------------------
__global__ __launch_bounds__(THREADS) void classpass(const float* __restrict__ x,
                                                     float* __restrict__ out) {
    __shared__ int   s_m;
    __shared__ int   s_head[CPB];
    __shared__ float s_n[CPB];
    __shared__ float s_wsum[WPB];

    int tid  = threadIdx.x;
    int lane = tid & 31;
    int wid  = tid >> 5;

    if (tid == 0) s_m = 0;
    int c = blockIdx.x * CPB + tid;             // prologue: no dependent data
    __syncthreads();

    cudaGridDependencySynchronize();            // wait for accum completion

    float contrib = 0.f;
    if (c < NC) {
        float4 sc = g_scal[c];                  // coalesced 16B
        if (sc.w > 0.f) {
            contrib = sc.x - A_D * sc.y + A_E * sc.z;
            if (sc.w == 1.f) {
                contrib -= A_S * sc.x;          // ||s||^2 == Q for n = 1
            } else {
                int p = atomicAdd(&s_m, 1);     // smem atomic
                s_head[p] = g_head[c];          // capture before reset
                s_n[p]    = sc.w;
            }
            g_scal[c] = make_float4(0.f, 0.f, 0.f, 0.f);    // restore invariant
            g_head[c] = 0;
        }
    }
    __syncthreads();

    int m = s_m;                                // ~3 multi classes per block
    for (int i = wid; i < m; i += WPB) {
        float4 a0 = make_float4(0.f, 0.f, 0.f, 0.f);
        float4 a1 = make_float4(0.f, 0.f, 0.f, 0.f);
        int a = s_head[i] - 1;
        while (a >= 0) {                        // walk the n-sample chain
            int nx = g_next[a];                 // broadcast; issues early
            const float4* xr = reinterpret_cast<const float4*>(x) + (size_t)a * F4;
            add4(a0, xr[lane]);
            add4(a1, xr[lane + 32]);
            a = nx - 1;
        }
        float ss = dot4(a0, a0) + dot4(a1, a1);
        #pragma unroll
        for (int o = 16; o > 0; o >>= 1)
            ss += __shfl_down_sync(0xFFFFFFFFu, ss, o);
        if (lane == 0) contrib -= A_S * ss / s_n[i];
    }

    #pragma unroll
    for (int o = 16; o > 0; o >>= 1)
        contrib += __shfl_down_sync(0xFFFFFFFFu, contrib, o);
    if (lane == 0) s_wsum[wid] = contrib;
    __syncthreads();

    if (tid == 0) {
        float b = 0.f;
        #pragma unroll
        for (int i = 0; i < WPB; i++) b += s_wsum[i];
        atomicAdd(&g_loss, b);                  // 391 ops, one addr: negligible
        __threadfence();
        if (atomicAdd(&g_done, 1u) == (unsigned)(gridDim.x - 1)) {
            out[0] = __ldcg(&g_loss) * (1.f / ((float)BATCH * (float)FEAT));
            g_loss = 0.f;                       // restore invariants
            g_done = 0u;
        }
    }
}

extern "C" void kernel_launch(void* const* d_in, const int* in_sizes, int n_in,
                              void* d_out, int out_size) {
    const float* x      = (const float*)d_in[0];   // batch_feature [16384, 256] f32
    const int*   label  = (const int*)d_in[1];     // batch_label   [16384] int32
    const float* center = (const float*)d_in[2];   // center_feature[100000, 256] f32
    float* out = (float*)d_out;

    accum<<<ACC_BLOCKS, THREADS>>>(x, center, label);

    // Programmatic dependent launch: classpass CTAs spin up during accum's
    // drain; cudaGridDependencySynchronize() inside provides the ordering.
    cudaLaunchConfig_t cfg = {};
    cfg.gridDim  = dim3(CLS_BLOCKS, 1, 1);
    cfg.blockDim = dim3(THREADS, 1, 1);
    cfg.dynamicSmemBytes = 0;
    cfg.stream = 0;
    cudaLaunchAttribute attr[1];
    attr[0].id = cudaLaunchAttributeProgrammaticStreamSerialization;
    attr[0].val.programmaticStreamSerializationAllowed = 1;
    cfg.attrs = attr;
    cfg.numAttrs = 1;
    cudaLaunchKernelEx(&cfg, classpass, x, out);
}

// round 17
// speedup vs baseline: 1.4837x; 1.0226x over previous
#include <cuda_runtime.h>
#include <cstdint>

#define NC         100000
#define FEAT       256
#define BATCH      16384
#define F4         64                          // FEAT / 4
#define ATHREADS   256
#define AWPB       8
#define ACC_BLOCKS (BATCH / AWPB)              // 2048 (one warp per sample)
#define CTHREADS   128
#define CWPB       4
#define CPB        128                         // classes scanned per block
#define CLS_BLOCKS ((NC + CPB - 1) / CPB)      // 782

// sum_i ||x_i - t_c||^2, t = 0.99c + 0.01 s/n:
//   P_c = sum_i [ q_i - 1.9602 (x_i.c) + 0.9801 ||c||^2 ]   (per-sample REDs)
//   contrib_c = P_c - 0.0199 ||s_c||^2 / n    (||s||^2 == Q for n = 1)
#define A_D 1.9602f
#define A_E 0.9801f
#define A_S 0.0199f

// Scratch — zero at module load; classpass restores the all-zero invariant.
// (g_next needs no invariant: every slot is unconditionally overwritten.)
__device__ float4   g_scal[NC];      // {P, Q, n, pad}  (1.6 MB)
__device__ int      g_head[NC];      // linked-list head, idx+1 (0 = empty)
__device__ int      g_next[BATCH];
__device__ float    g_loss;
__device__ unsigned g_done;

__device__ __forceinline__ void red_add_f32(float* addr, float v) {
    asm volatile("red.global.add.f32 [%0], %1;" :: "l"(addr), "f"(v) : "memory");
}
__device__ __forceinline__ float dot4(float4 a, float4 b) {
    return a.x*b.x + a.y*b.y + a.z*b.z + a.w*b.w;
}
__device__ __forceinline__ void add4(float4& a, float4 b) {
    a.x += b.x; a.y += b.y; a.z += b.z; a.w += b.w;
}

// ---------------------------------------------------------------------------
// Launch 1: one warp per sample. Streamed x row + gathered center row; fold
// the separable loss terms into ONE scalar P per sample; lane 0 REDs
// {P, Q, 1} into g_scal[c] and pushes the sample onto its class list.
// ---------------------------------------------------------------------------
__global__ __launch_bounds__(ATHREADS) void accum(const float* __restrict__ x,
                                                  const float* __restrict__ center,
                                                  const int* __restrict__ label) {
    int w    = (blockIdx.x * ATHREADS + threadIdx.x) >> 5;  // sample id
    int lane = threadIdx.x & 31;
    int c    = label[w];                                    // broadcast load

    const float4* xr = reinterpret_cast<const float4*>(x)      + (size_t)w * F4;
    const float4* cr = reinterpret_cast<const float4*>(center) + (size_t)c * F4;
    float4 v0 = xr[lane], v1 = xr[lane + 32];
    float4 c0 = cr[lane], c1 = cr[lane + 32];

    float q = dot4(v0, v0) + dot4(v1, v1);
    float p = q - A_D * (dot4(v0, c0) + dot4(v1, c1))
                + A_E * (dot4(c0, c0) + dot4(c1, c1));
    #pragma unroll
    for (int o = 16; o > 0; o >>= 1) {
        q += __shfl_down_sync(0xFFFFFFFFu, q, o);
        p += __shfl_down_sync(0xFFFFFFFFu, p, o);
    }
    if (lane == 0) {
        g_next[w] = atomicExch(&g_head[c], w + 1);          // list push
        float* base = reinterpret_cast<float*>(&g_scal[c]);
        red_add_f32(base + 0, p);
        red_add_f32(base + 1, q);
        red_add_f32(base + 2, 1.0f);
    }
}

// ---------------------------------------------------------------------------
// Launch 2: coalesced scan of g_scal + g_head loaded IN PARALLEL (no
// dependent round trip). n=1 closes inline with P - A_S*Q; multi classes
// (~1.2K) get a warp chain-walk over x rows. 782 small CTAs for latency
// spread. g_loss atomic + last-block writes d_out. Invariants restored.
// ---------------------------------------------------------------------------
__global__ __launch_bounds__(CTHREADS) void classpass(const float* __restrict__ x,
                                                      float* __restrict__ out) {
    __shared__ int   s_m;
    __shared__ int   s_head[CPB];
    __shared__ float s_n[CPB];
    __shared__ float s_wsum[CWPB];

    int tid  = threadIdx.x;
    int lane = tid & 31;
    int wid  = tid >> 5;

    if (tid == 0) s_m = 0;
    __syncthreads();

    float acc = 0.f;
    int c = blockIdx.x * CPB + tid;
    if (c < NC) {
        float4 sc = g_scal[c];                 // coalesced 16B
        int    h  = g_head[c];                 // coalesced 4B, independent load
        if (sc.z > 0.f) {
            if (sc.z == 1.f) {
                acc = sc.x - A_S * sc.y;       // ||s||^2 == Q for n = 1
            } else {
                int p = atomicAdd(&s_m, 1);    // smem atomic
                s_head[p] = h;
                s_n[p]    = sc.z;
                acc = sc.x;
            }
            g_scal[c] = make_float4(0.f, 0.f, 0.f, 0.f);   // restore invariant
            g_head[c] = 0;
        }
    }
    __syncthreads();

    int m = s_m;                               // ~1.5 multi chains per block
    for (int i = wid; i < m; i += CWPB) {
        float4 a0 = make_float4(0.f, 0.f, 0.f, 0.f);
        float4 a1 = make_float4(0.f, 0.f, 0.f, 0.f);
        int a = s_head[i] - 1;
        while (a >= 0) {                       // avg ~2.2 hops
            int nx = g_next[a];                // broadcast; issues early
            const float4* xr = reinterpret_cast<const float4*>(x) + (size_t)a * F4;
            add4(a0, xr[lane]);
            add4(a1, xr[lane + 32]);
            a = nx - 1;
        }
        float ss = dot4(a0, a0) + dot4(a1, a1);
        #pragma unroll
        for (int o = 16; o > 0; o >>= 1)
            ss += __shfl_down_sync(0xFFFFFFFFu, ss, o);
        if (lane == 0) acc -= A_S * ss / s_n[i];
    }

    #pragma unroll
    for (int o = 16; o > 0; o >>= 1)
        acc += __shfl_down_sync(0xFFFFFFFFu, acc, o);
    if (lane == 0) s_wsum[wid] = acc;
    __syncthreads();

    if (tid == 0) {
        float b = 0.f;
        #pragma unroll
        for (int i = 0; i < CWPB; i++) b += s_wsum[i];
        atomicAdd(&g_loss, b);                 // 782 ops, one addr: negligible
        __threadfence();
        if (atomicAdd(&g_done, 1u) == (unsigned)(gridDim.x - 1)) {
            out[0] = __ldcg(&g_loss) * (1.f / ((float)BATCH * (float)FEAT));
            g_loss = 0.f;                      // restore invariants
            g_done = 0u;
        }
    }
}

extern "C" void kernel_launch(void* const* d_in, const int* in_sizes, int n_in,
                              void* d_out, int out_size) {
    const float* x      = (const float*)d_in[0];   // batch_feature [16384, 256] f32
    const int*   label  = (const int*)d_in[1];     // batch_label   [16384] int32
    const float* center = (const float*)d_in[2];   // center_feature[100000, 256] f32
    float* out = (float*)d_out;

    accum    <<<ACC_BLOCKS, ATHREADS>>>(x, center, label);
    classpass<<<CLS_BLOCKS, CTHREADS>>>(x, out);
}